// round 8
// baseline (speedup 1.0000x reference)
#include <cuda_runtime.h>
#include <cstdint>

#define BB 64
#define TT 1024
#define DD 64
#define HH 256
#define NGRP 4        // batch groups per layer (16 batches each)
#define NBAT 16       // batches per group
#define NT 256

typedef unsigned long long ull;

// ---------------- device-global scratch ----------------
__device__ float    d_h1s[(size_t)TT * NGRP * HH * 16];   // l0 hidden stream k-major [T][grp][H][16b]
__device__ float    d_hbA[4 * NGRP * HH * 16];            // l0 h rotation [4][grp][H][16b]
__device__ float    d_hbB[4 * NGRP * HH * 16];            // l1 h rotation
__device__ float    d_h2s[BB * HH];                       // l1 final h [B][H]
__device__ unsigned d_flag[2 * NGRP * 16];                // monotonic per-slice progress

__device__ __forceinline__ ull splat2(float w) {
    ull d; asm("mov.b64 %0, {%1, %1};" : "=l"(d) : "f"(w)); return d;
}
__device__ __forceinline__ void fma2(ull& d, ull a, ull b) {
    asm("fma.rn.f32x2 %0, %1, %2, %0;" : "+l"(d) : "l"(a), "l"(b));
}
__device__ __forceinline__ float sigf(float x)   { return 1.f / (1.f + __expf(-x)); }
__device__ __forceinline__ float tanhfs(float x) { return 1.f - 2.f / (1.f + __expf(2.f * x)); }
__device__ __forceinline__ void st_release(unsigned* p, unsigned v) {
    asm volatile("st.global.release.gpu.u32 [%0], %1;" :: "l"(p), "r"(v) : "memory");
}
__device__ __forceinline__ unsigned ld_acquire(const unsigned* p) {
    unsigned v; asm volatile("ld.global.acquire.gpu.u32 %0, [%1];" : "=r"(v) : "l"(p)); return v;
}

// wait (lanes 0,1) until flags[s0] and flags[s0+1] reach tgt, then warp-converge
__device__ __forceinline__ void wait2(const unsigned* flags, int s0, unsigned tgt, int lane) {
    if (lane < 2) {
        const unsigned* f = flags + s0 + lane;
        while (ld_acquire(f) < tgt) {}
    }
    __syncwarp(0xFFFFFFFFu);
}

// accumulate NCH chunks of 4 k-rows: 2 gate rows x 16 batches (f32x2 pairs)
template <int NCH>
__device__ __forceinline__ void gemm_part(const float* __restrict__ wA,
                                          const float* __restrict__ wB,
                                          const float* __restrict__ vk0,
                                          ull* aA, ull* aB)
{
#pragma unroll
    for (int c = 0; c < NCH; ++c) {
        float4 wa = *reinterpret_cast<const float4*>(wA + 4 * c);
        float4 wb = *reinterpret_cast<const float4*>(wB + 4 * c);
        const float* vk = vk0 + 4 * c * 16;
#pragma unroll
        for (int j = 0; j < 4; ++j) {
            const ulonglong2* vp = reinterpret_cast<const ulonglong2*>(vk + j * 16);
            ulonglong2 q0 = vp[0], q1 = vp[1], q2 = vp[2], q3 = vp[3];
            float fa = (j == 0) ? wa.x : (j == 1) ? wa.y : (j == 2) ? wa.z : wa.w;
            float fb = (j == 0) ? wb.x : (j == 1) ? wb.y : (j == 2) ? wb.z : wb.w;
            ull wsa = splat2(fa), wsb = splat2(fb);
            fma2(aA[0], wsa, q0.x); fma2(aA[1], wsa, q0.y);
            fma2(aA[2], wsa, q1.x); fma2(aA[3], wsa, q1.y);
            fma2(aA[4], wsa, q2.x); fma2(aA[5], wsa, q2.y);
            fma2(aA[6], wsa, q3.x); fma2(aA[7], wsa, q3.y);
            fma2(aB[0], wsb, q0.x); fma2(aB[1], wsb, q0.y);
            fma2(aB[2], wsb, q1.x); fma2(aB[3], wsb, q1.y);
            fma2(aB[4], wsb, q2.x); fma2(aB[5], wsb, q2.y);
            fma2(aB[6], wsb, q3.x); fma2(aB[7], wsb, q3.y);
        }
    }
}

// One LSTM layer, persistent. CTA = 16 units x 16 batches (64 gate rows).
// Warp w consumes h slices {2w, 2w+1} only; h[t+1] is prefetched into registers
// before the x-gemm so its L2 round-trip overlaps compute.
template <int KIN, int LAYER>
__device__ __forceinline__ void layer_body(
    const float* __restrict__ in0,           // l0: x [B][T][D]; l1: d_h1s k-major [T][grp][H][16]
    const float* __restrict__ Wih, const float* __restrict__ Whh,
    const float* __restrict__ bih, const float* __restrict__ bhh,
    float* hb, float* hstream, int grp, int slice)
{
    constexpr int KTOT = KIN + HH;
    constexpr int SP   = KTOT + 4;      // weight row stride
    constexpr int XQ   = KIN / 8;       // per-warp x-k span (l0: 8, l1: 32)
    constexpr int HQ   = HH / 8;        // per-warp h-k span (32)
    constexpr int PK   = 64 * 18;
    constexpr int XR   = XQ / 8;        // per-lane float4 count for x (l1: 4)
    constexpr int HR   = HQ / 8;        // per-lane float4 count for h (4)

    extern __shared__ float sm[];
    float* sW = sm;                     // [64][SP]
    float* sV = sW + 64 * SP;           // [KTOT][16]  (x | h), k-major
    float* sP = sV + KTOT * 16;         // [8][64][18]
    float* sB = sP + 8 * PK;            // [64]
    float* sC = sB + 64;                // [256] cell (u*16+b)

    const int tid   = threadIdx.x;
    const int bbase = grp * NBAT;
    const int ubase = slice * 16;
    unsigned* ownflags = &d_flag[(LAYER * NGRP + grp) * 16];
    unsigned* srcflags = &d_flag[grp * 16];               // layer-0 flags (l1 x-dep)
    unsigned* myflag   = ownflags + slice;
    const unsigned fbase = *(volatile unsigned*)myflag;   // lockstep across all flags

    for (int idx = tid; idx < 64 * KTOT; idx += NT) {
        int r = idx / KTOT, k = idx - r * KTOT;
        int R = ((r >> 4) << 8) + ubase + (r & 15);
        sW[r * SP + k] = (k < KIN) ? Wih[(long long)R * KIN + k]
                                   : Whh[(long long)R * HH + (k - KIN)];
    }
    if (tid < 64) {
        int R = ((tid >> 4) << 8) + ubase + (tid & 15);
        sB[tid] = bih[R] + bhh[R];
    }
    sC[tid] = 0.f;
    if (tid < 64) {   // zero own slice of rotation buffer 0 (h_{-1})
        float4 z = make_float4(0.f, 0.f, 0.f, 0.f);
        int u = tid >> 2, q = tid & 3;
        *reinterpret_cast<float4*>(hb + ((size_t)(0 * NGRP + grp) * HH + ubase + u) * 16 + q * 4) = z;
    }
    __syncthreads();
    if (tid == 0) st_release(myflag, fbase + 1);

    const int w    = tid >> 5;
    const int lane = tid & 31;
    const float* wAx = sW + lane * SP + w * XQ;
    const float* wBx = sW + (lane + 32) * SP + w * XQ;
    const float* wAh = sW + lane * SP + KIN + w * HQ;
    const float* wBh = sW + (lane + 32) * SP + KIN + w * HQ;
    const float* vx  = sV + (w * XQ) * 16;
    const float* vh  = sV + (KIN + w * HQ) * 16;
    float4* xdstv = reinterpret_cast<float4*>(sV) + (w * XQ) * 4;          // l1 x chunk
    float4* hdstv = reinterpret_cast<float4*>(sV) + (KIN + w * HQ) * 4;    // h chunk

    // l0 x staging (in-warp transpose): lane -> (batch lane>>1, 4 k-values)
    const float* xsrc0 = in0 + (size_t)(bbase + (lane >> 1)) * TT * DD + w * XQ + (lane & 1) * 4;
    float* xdst0 = sV + (w * XQ + (lane & 1) * 4) * 16 + (lane >> 1);

    ull aA[8], aB[8];
    float4 hr[HR];
    float4 xr1[XR > 0 ? XR : 1];
    float4 xr0;

    // ---- prologue: x-part for t = 0, then prefetch h[0] ----
#pragma unroll
    for (int i = 0; i < 8; ++i) { aA[i] = 0; aB[i] = 0; }
    if (LAYER == 0) {
        float4 v = *reinterpret_cast<const float4*>(xsrc0);
        xdst0[0] = v.x; xdst0[16] = v.y; xdst0[32] = v.z; xdst0[48] = v.w;
    } else {
        wait2(srcflags, 2 * w, fbase + 2u, lane);
        const float4* src = reinterpret_cast<const float4*>(in0) + ((size_t)(0 * NGRP + grp) * KIN + w * XQ) * 4;
#pragma unroll
        for (int i = 0; i < XR; ++i) xdstv[lane + 32 * i] = __ldcv(src + lane + 32 * i);
    }
    __syncwarp(0xFFFFFFFFu);
    gemm_part<XQ / 4>(wAx, wBx, vx, aA, aB);

    wait2(ownflags, 2 * w, fbase + 1u, lane);
    {
        const float4* src = reinterpret_cast<const float4*>(hb) +
                            ((size_t)(0 * NGRP + grp) * HH + w * HQ) * 4;
#pragma unroll
        for (int i = 0; i < HR; ++i) hr[i] = __ldcv(src + lane + 32 * i);
    }

    for (int t = 0; t < TT; ++t) {
        // ---- [A] commit prefetched h[t] to smem, h-gemm ----
#pragma unroll
        for (int i = 0; i < HR; ++i) hdstv[lane + 32 * i] = hr[i];
        __syncwarp(0xFFFFFFFFu);
        gemm_part<HQ / 4>(wAh, wBh, vh, aA, aB);
        {
            ull* pA = reinterpret_cast<ull*>(sP + w * PK + lane * 18);
            ull* pB = reinterpret_cast<ull*>(sP + w * PK + (lane + 32) * 18);
#pragma unroll
            for (int bp = 0; bp < 8; ++bp) { pA[bp] = aA[bp]; pB[bp] = aB[bp]; }
        }
        __syncthreads();

        // ---- [B] fused reduce + pointwise + coalesced publish ----
        {
            int u = tid >> 4, b = tid & 15;
            float gv[4];
#pragma unroll
            for (int g = 0; g < 4; ++g) {
                int r = g * 16 + u;
                float s = sB[r];
#pragma unroll
                for (int q = 0; q < 8; ++q) s += sP[q * PK + r * 18 + b];
                gv[g] = s;
            }
            float iv = sigf(gv[0]);
            float fv = sigf(gv[1]);
            float gg = tanhfs(gv[2]);
            float ov = sigf(gv[3]);
            float c  = fv * sC[tid] + iv * gg;
            sC[tid] = c;
            float hv = ov * tanhfs(c);
            hb[((size_t)((((t + 1) & 3) * NGRP) + grp) * HH + ubase + u) * 16 + b] = hv;
            if (LAYER == 0)
                hstream[((size_t)(t * NGRP + grp) * HH + ubase + u) * 16 + b] = hv;
            if (LAYER == 1 && t == TT - 1)
                d_h2s[(size_t)(bbase + b) * HH + ubase + u] = hv;
        }
        __syncthreads();            // publish issued by all; sP consumed
        if (tid == 0) st_release(myflag, fbase + (unsigned)t + 2u);

        // ---- [C] tail: stage x[t+1], prefetch h[t+1] into regs, x-gemm ----
        if (t + 1 < TT) {
#pragma unroll
            for (int i = 0; i < 8; ++i) { aA[i] = 0; aB[i] = 0; }
            if (LAYER == 0) {
                xr0 = *reinterpret_cast<const float4*>(xsrc0 + (size_t)(t + 1) * DD);
            } else {
                wait2(srcflags, 2 * w, fbase + (unsigned)t + 3u, lane);
                const float4* src = reinterpret_cast<const float4*>(in0) +
                                    ((size_t)((t + 1) * NGRP + grp) * KIN + w * XQ) * 4;
#pragma unroll
                for (int i = 0; i < XR; ++i) xr1[i] = __ldcv(src + lane + 32 * i);
            }
            // early h wait + prefetch (LDGs overlap the x-gemm below)
            wait2(ownflags, 2 * w, fbase + (unsigned)t + 2u, lane);
            {
                const float4* src = reinterpret_cast<const float4*>(hb) +
                                    ((size_t)(((t + 1) & 3) * NGRP + grp) * HH + w * HQ) * 4;
#pragma unroll
                for (int i = 0; i < HR; ++i) hr[i] = __ldcv(src + lane + 32 * i);
            }
            // commit x to smem, compute x-part
            if (LAYER == 0) {
                xdst0[0] = xr0.x; xdst0[16] = xr0.y; xdst0[32] = xr0.z; xdst0[48] = xr0.w;
            } else {
#pragma unroll
                for (int i = 0; i < XR; ++i) xdstv[lane + 32 * i] = xr1[i];
            }
            __syncwarp(0xFFFFFFFFu);
            gemm_part<XQ / 4>(wAx, wBx, vx, aA, aB);
        }
    }
}

__global__ void __launch_bounds__(NT, 1) rnn_fused(
    const float* __restrict__ x,
    const float* __restrict__ Wih0, const float* __restrict__ Whh0,
    const float* __restrict__ bih0, const float* __restrict__ bhh0,
    const float* __restrict__ Wih1, const float* __restrict__ Whh1,
    const float* __restrict__ bih1, const float* __restrict__ bhh1)
{
    int bid   = blockIdx.x;
    int layer = bid >> 6;
    int sub   = bid & 63;
    int grp   = sub >> 4;
    int slice = sub & 15;

    if (layer == 0) {
        layer_body<DD, 0>(x, Wih0, Whh0, bih0, bhh0, d_hbA, d_h1s, grp, slice);
    } else {
        layer_body<HH, 1>(d_h1s, Wih1, Whh1, bih1, bhh1, d_hbB, nullptr, grp, slice);
    }
}

// out[b] = dot(h2_last[b][:], fc_w) + fc_b
__global__ void fc_kernel(const float* __restrict__ fcw,
                          const float* __restrict__ fcb,
                          float* __restrict__ out)
{
    int b = blockIdx.x, tid = threadIdx.x;
    const float* h = d_h2s + (size_t)b * HH;
    float s = 0.f;
    for (int k = tid; k < HH; k += 128) s += h[k] * fcw[k];
    for (int o = 16; o > 0; o >>= 1) s += __shfl_xor_sync(0xFFFFFFFFu, s, o);
    __shared__ float ws[4];
    if ((tid & 31) == 0) ws[tid >> 5] = s;
    __syncthreads();
    if (tid == 0) out[b] = ws[0] + ws[1] + ws[2] + ws[3] + fcb[0];
}

extern "C" void kernel_launch(void* const* d_in, const int* in_sizes, int n_in,
                              void* d_out, int out_size)
{
    const float* x     = (const float*)d_in[0];
    const float* W_ih0 = (const float*)d_in[1];
    const float* W_hh0 = (const float*)d_in[2];
    const float* b_ih0 = (const float*)d_in[3];
    const float* b_hh0 = (const float*)d_in[4];
    const float* W_ih1 = (const float*)d_in[5];
    const float* W_hh1 = (const float*)d_in[6];
    const float* b_ih1 = (const float*)d_in[7];
    const float* b_hh1 = (const float*)d_in[8];
    const float* fc_w  = (const float*)d_in[9];
    const float* fc_b  = (const float*)d_in[10];
    float* out = (float*)d_out;

    // smem sized for layer-1 layout: sW + sV + sP + sB + sC
    const int SMB = (64 * (HH + HH + 4) + (HH + HH) * 16 + 8 * 64 * 18 + 64 + 256) * 4; // 203,008

    cudaFuncSetAttribute(rnn_fused, cudaFuncAttributeMaxDynamicSharedMemorySize, SMB);

    rnn_fused<<<128, NT, SMB>>>(x, W_ih0, W_hh0, b_ih0, b_hh0,
                                W_ih1, W_hh1, b_ih1, b_hh1);
    fc_kernel<<<BB, 128>>>(fc_w, fc_b, out);
}

// round 9
// speedup vs baseline: 1.5352x; 1.5352x over previous
#include <cuda_runtime.h>
#include <cstdint>

#define BB 64
#define TT 1024
#define DD 64
#define HH 256
#define NGRP 4        // batch groups per layer (16 batches each)
#define NBAT 16       // batches per group
#define NT 256

typedef unsigned long long ull;

// ---------------- device-global scratch ----------------
__device__ float    d_h1s[(size_t)TT * NGRP * HH * 16];   // l0 hidden stream k-major [T][grp][H][16b]
__device__ float    d_hbA[4 * NGRP * HH * 16];            // l0 h rotation [4][grp][H][16b]
__device__ float    d_hbB[4 * NGRP * HH * 16];            // l1 h rotation
__device__ float    d_h2s[BB * HH];                       // l1 final h [B][H]
__device__ unsigned d_flag[2 * NGRP * 16];                // monotonic per-slice progress

__device__ __forceinline__ ull splat2(float w) {
    ull d; asm("mov.b64 %0, {%1, %1};" : "=l"(d) : "f"(w)); return d;
}
__device__ __forceinline__ void fma2(ull& d, ull a, ull b) {
    asm("fma.rn.f32x2 %0, %1, %2, %0;" : "+l"(d) : "l"(a), "l"(b));
}
__device__ __forceinline__ float sigf(float x)   { return 1.f / (1.f + __expf(-x)); }
__device__ __forceinline__ float tanhfs(float x) { return 1.f - 2.f / (1.f + __expf(2.f * x)); }
__device__ __forceinline__ void st_release(unsigned* p, unsigned v) {
    asm volatile("st.global.release.gpu.u32 [%0], %1;" :: "l"(p), "r"(v) : "memory");
}
__device__ __forceinline__ unsigned ld_acquire(const unsigned* p) {
    unsigned v; asm volatile("ld.global.acquire.gpu.u32 %0, [%1];" : "=r"(v) : "l"(p)); return v;
}

// wait (lanes 0,1) until flags[s0] and flags[s0+1] reach tgt, then warp-converge
__device__ __forceinline__ void wait2(const unsigned* flags, int s0, unsigned tgt, int lane) {
    if (lane < 2) {
        const unsigned* f = flags + s0 + lane;
        while (ld_acquire(f) < tgt) {}
    }
    __syncwarp(0xFFFFFFFFu);
}

// accumulate NCH chunks of 4 k-rows: 2 gate rows x 16 batches (f32x2 pairs)
template <int NCH>
__device__ __forceinline__ void gemm_part(const float* __restrict__ wA,
                                          const float* __restrict__ wB,
                                          const float* __restrict__ vk0,
                                          ull* aA, ull* aB)
{
#pragma unroll
    for (int c = 0; c < NCH; ++c) {
        float4 wa = *reinterpret_cast<const float4*>(wA + 4 * c);
        float4 wb = *reinterpret_cast<const float4*>(wB + 4 * c);
        const float* vk = vk0 + 4 * c * 16;
#pragma unroll
        for (int j = 0; j < 4; ++j) {
            const ulonglong2* vp = reinterpret_cast<const ulonglong2*>(vk + j * 16);
            ulonglong2 q0 = vp[0], q1 = vp[1], q2 = vp[2], q3 = vp[3];
            float fa = (j == 0) ? wa.x : (j == 1) ? wa.y : (j == 2) ? wa.z : wa.w;
            float fb = (j == 0) ? wb.x : (j == 1) ? wb.y : (j == 2) ? wb.z : wb.w;
            ull wsa = splat2(fa), wsb = splat2(fb);
            fma2(aA[0], wsa, q0.x); fma2(aA[1], wsa, q0.y);
            fma2(aA[2], wsa, q1.x); fma2(aA[3], wsa, q1.y);
            fma2(aA[4], wsa, q2.x); fma2(aA[5], wsa, q2.y);
            fma2(aA[6], wsa, q3.x); fma2(aA[7], wsa, q3.y);
            fma2(aB[0], wsb, q0.x); fma2(aB[1], wsb, q0.y);
            fma2(aB[2], wsb, q1.x); fma2(aB[3], wsb, q1.y);
            fma2(aB[4], wsb, q2.x); fma2(aB[5], wsb, q2.y);
            fma2(aB[6], wsb, q3.x); fma2(aB[7], wsb, q3.y);
        }
    }
}

// One LSTM layer, persistent. CTA = 16 units x 16 batches (64 gate rows).
// Warp w consumes h slices {2w, 2w+1} only. Tail order (critical): x-gemm half 1
// runs BEFORE the own-flag wait; h[t+1] LDGs are issued mid-x-gemm so their L2
// round-trip overlaps x-gemm half 2.
template <int KIN, int LAYER>
__device__ __forceinline__ void layer_body(
    const float* __restrict__ in0,           // l0: x [B][T][D]; l1: d_h1s k-major [T][grp][H][16]
    const float* __restrict__ Wih, const float* __restrict__ Whh,
    const float* __restrict__ bih, const float* __restrict__ bhh,
    float* hb, float* hstream, int grp, int slice)
{
    constexpr int KTOT = KIN + HH;
    constexpr int SP   = KTOT + 4;      // weight row stride
    constexpr int XQ   = KIN / 8;       // per-warp x-k span (l0: 8, l1: 32)
    constexpr int HQ   = HH / 8;        // per-warp h-k span (32)
    constexpr int PK   = 64 * 18;
    constexpr int XR   = XQ / 8;        // per-lane float4 count for x (l1: 4)
    constexpr int HR   = HQ / 8;        // per-lane float4 count for h (4)
    constexpr int XC   = XQ / 4;        // x chunks (l0: 2, l1: 8)
    constexpr int XC1  = XC / 2;        // x-gemm half 1
    constexpr int XC2  = XC - XC1;      // x-gemm half 2

    extern __shared__ float sm[];
    float* sW = sm;                     // [64][SP]
    float* sV = sW + 64 * SP;           // [KTOT][16]  (x | h), k-major
    float* sP = sV + KTOT * 16;         // [8][64][18]
    float* sB = sP + 8 * PK;            // [64]
    float* sC = sB + 64;                // [256] cell (u*16+b)

    const int tid   = threadIdx.x;
    const int bbase = grp * NBAT;
    const int ubase = slice * 16;
    unsigned* ownflags = &d_flag[(LAYER * NGRP + grp) * 16];
    unsigned* srcflags = &d_flag[grp * 16];               // layer-0 flags (l1 x-dep)
    unsigned* myflag   = ownflags + slice;
    const unsigned fbase = *(volatile unsigned*)myflag;   // lockstep across all flags

    for (int idx = tid; idx < 64 * KTOT; idx += NT) {
        int r = idx / KTOT, k = idx - r * KTOT;
        int R = ((r >> 4) << 8) + ubase + (r & 15);
        sW[r * SP + k] = (k < KIN) ? Wih[(long long)R * KIN + k]
                                   : Whh[(long long)R * HH + (k - KIN)];
    }
    if (tid < 64) {
        int R = ((tid >> 4) << 8) + ubase + (tid & 15);
        sB[tid] = bih[R] + bhh[R];
    }
    sC[tid] = 0.f;
    if (tid < 64) {   // zero own slice of rotation buffer 0 (h_{-1})
        float4 z = make_float4(0.f, 0.f, 0.f, 0.f);
        int u = tid >> 2, q = tid & 3;
        *reinterpret_cast<float4*>(hb + ((size_t)(0 * NGRP + grp) * HH + ubase + u) * 16 + q * 4) = z;
    }
    __syncthreads();
    if (tid == 0) st_release(myflag, fbase + 1);

    const int w    = tid >> 5;
    const int lane = tid & 31;
    const float* wAx = sW + lane * SP + w * XQ;
    const float* wBx = sW + (lane + 32) * SP + w * XQ;
    const float* wAh = sW + lane * SP + KIN + w * HQ;
    const float* wBh = sW + (lane + 32) * SP + KIN + w * HQ;
    const float* vx  = sV + (w * XQ) * 16;
    const float* vh  = sV + (KIN + w * HQ) * 16;
    float4* xdstv = reinterpret_cast<float4*>(sV) + (w * XQ) * 4;          // l1 x chunk
    float4* hdstv = reinterpret_cast<float4*>(sV) + (KIN + w * HQ) * 4;    // h chunk

    // l0 x staging (in-warp transpose): lane -> (batch lane>>1, 4 k-values)
    const float* xsrc0 = in0 + (size_t)(bbase + (lane >> 1)) * TT * DD + w * XQ + (lane & 1) * 4;
    float* xdst0 = sV + (w * XQ + (lane & 1) * 4) * 16 + (lane >> 1);

    ull aA[8], aB[8];
    float4 hr[HR];

    // ---- prologue: x-part for t=0, then wait + prefetch h[0] ----
#pragma unroll
    for (int i = 0; i < 8; ++i) { aA[i] = 0; aB[i] = 0; }
    if (LAYER == 0) {
        float4 v = *reinterpret_cast<const float4*>(xsrc0);
        xdst0[0] = v.x; xdst0[16] = v.y; xdst0[32] = v.z; xdst0[48] = v.w;
    } else {
        wait2(srcflags, 2 * w, fbase + 2u, lane);
        const float4* src = reinterpret_cast<const float4*>(in0) + ((size_t)(0 * NGRP + grp) * KIN + w * XQ) * 4;
#pragma unroll
        for (int i = 0; i < XR; ++i) xdstv[lane + 32 * i] = __ldcv(src + lane + 32 * i);
    }
    __syncwarp(0xFFFFFFFFu);
    gemm_part<XC>(wAx, wBx, vx, aA, aB);

    wait2(ownflags, 2 * w, fbase + 1u, lane);
    {
        const float4* src = reinterpret_cast<const float4*>(hb) +
                            ((size_t)(0 * NGRP + grp) * HH + w * HQ) * 4;
#pragma unroll
        for (int i = 0; i < HR; ++i) hr[i] = __ldcv(src + lane + 32 * i);
    }

    for (int t = 0; t < TT; ++t) {
        // ---- [A] commit prefetched h[t] to smem, h-gemm ----
#pragma unroll
        for (int i = 0; i < HR; ++i) hdstv[lane + 32 * i] = hr[i];
        __syncwarp(0xFFFFFFFFu);
        gemm_part<HQ / 4>(wAh, wBh, vh, aA, aB);
        {
            ull* pA = reinterpret_cast<ull*>(sP + w * PK + lane * 18);
            ull* pB = reinterpret_cast<ull*>(sP + w * PK + (lane + 32) * 18);
#pragma unroll
            for (int bp = 0; bp < 8; ++bp) { pA[bp] = aA[bp]; pB[bp] = aB[bp]; }
        }
        __syncthreads();

        // ---- [B] fused reduce + pointwise + coalesced publish ----
        {
            int u = tid >> 4, b = tid & 15;
            float gv[4];
#pragma unroll
            for (int g = 0; g < 4; ++g) {
                int r = g * 16 + u;
                float s = sB[r];
#pragma unroll
                for (int q = 0; q < 8; ++q) s += sP[q * PK + r * 18 + b];
                gv[g] = s;
            }
            float iv = sigf(gv[0]);
            float fv = sigf(gv[1]);
            float gg = tanhfs(gv[2]);
            float ov = sigf(gv[3]);
            float c  = fv * sC[tid] + iv * gg;
            sC[tid] = c;
            float hv = ov * tanhfs(c);
            hb[((size_t)((((t + 1) & 3) * NGRP) + grp) * HH + ubase + u) * 16 + b] = hv;
            if (LAYER == 0)
                hstream[((size_t)(t * NGRP + grp) * HH + ubase + u) * 16 + b] = hv;
            if (LAYER == 1 && t == TT - 1)
                d_h2s[(size_t)(bbase + b) * HH + ubase + u] = hv;
        }
        __syncthreads();            // publish issued by all; sP consumed
        if (tid == 0) st_release(myflag, fbase + (unsigned)t + 2u);

        // ---- [C] tail: stage x[t+1]; x-gemm half1; wait + prefetch h[t+1]; x-gemm half2 ----
        if (t + 1 < TT) {
#pragma unroll
            for (int i = 0; i < 8; ++i) { aA[i] = 0; aB[i] = 0; }
            if (LAYER == 0) {
                float4 v = *reinterpret_cast<const float4*>(xsrc0 + (size_t)(t + 1) * DD);
                xdst0[0] = v.x; xdst0[16] = v.y; xdst0[32] = v.z; xdst0[48] = v.w;
            } else {
                wait2(srcflags, 2 * w, fbase + (unsigned)t + 3u, lane);
                const float4* src = reinterpret_cast<const float4*>(in0) +
                                    ((size_t)((t + 1) * NGRP + grp) * KIN + w * XQ) * 4;
#pragma unroll
                for (int i = 0; i < XR; ++i) xdstv[lane + 32 * i] = __ldcv(src + lane + 32 * i);
            }
            __syncwarp(0xFFFFFFFFu);

            // x-gemm half 1 (no own-flag dependency -> overlaps peer skew)
            gemm_part<XC1>(wAx, wBx, vx, aA, aB);

            // by now peers have had ~1k cycles since our release: wait is ~free;
            // prefetch h[t+1] LDGs fly during x-gemm half 2
            wait2(ownflags, 2 * w, fbase + (unsigned)t + 2u, lane);
            {
                const float4* src = reinterpret_cast<const float4*>(hb) +
                                    ((size_t)(((t + 1) & 3) * NGRP + grp) * HH + w * HQ) * 4;
#pragma unroll
                for (int i = 0; i < HR; ++i) hr[i] = __ldcv(src + lane + 32 * i);
            }

            gemm_part<XC2>(wAx + 4 * XC1, wBx + 4 * XC1, vx + 4 * XC1 * 16, aA, aB);
        }
    }
}

__global__ void __launch_bounds__(NT, 1) rnn_fused(
    const float* __restrict__ x,
    const float* __restrict__ Wih0, const float* __restrict__ Whh0,
    const float* __restrict__ bih0, const float* __restrict__ bhh0,
    const float* __restrict__ Wih1, const float* __restrict__ Whh1,
    const float* __restrict__ bih1, const float* __restrict__ bhh1)
{
    int bid   = blockIdx.x;
    int layer = bid >> 6;
    int sub   = bid & 63;
    int grp   = sub >> 4;
    int slice = sub & 15;

    if (layer == 0) {
        layer_body<DD, 0>(x, Wih0, Whh0, bih0, bhh0, d_hbA, d_h1s, grp, slice);
    } else {
        layer_body<HH, 1>(d_h1s, Wih1, Whh1, bih1, bhh1, d_hbB, nullptr, grp, slice);
    }
}

// out[b] = dot(h2_last[b][:], fc_w) + fc_b
__global__ void fc_kernel(const float* __restrict__ fcw,
                          const float* __restrict__ fcb,
                          float* __restrict__ out)
{
    int b = blockIdx.x, tid = threadIdx.x;
    const float* h = d_h2s + (size_t)b * HH;
    float s = 0.f;
    for (int k = tid; k < HH; k += 128) s += h[k] * fcw[k];
    for (int o = 16; o > 0; o >>= 1) s += __shfl_xor_sync(0xFFFFFFFFu, s, o);
    __shared__ float ws[4];
    if ((tid & 31) == 0) ws[tid >> 5] = s;
    __syncthreads();
    if (tid == 0) out[b] = ws[0] + ws[1] + ws[2] + ws[3] + fcb[0];
}

extern "C" void kernel_launch(void* const* d_in, const int* in_sizes, int n_in,
                              void* d_out, int out_size)
{
    const float* x     = (const float*)d_in[0];
    const float* W_ih0 = (const float*)d_in[1];
    const float* W_hh0 = (const float*)d_in[2];
    const float* b_ih0 = (const float*)d_in[3];
    const float* b_hh0 = (const float*)d_in[4];
    const float* W_ih1 = (const float*)d_in[5];
    const float* W_hh1 = (const float*)d_in[6];
    const float* b_ih1 = (const float*)d_in[7];
    const float* b_hh1 = (const float*)d_in[8];
    const float* fc_w  = (const float*)d_in[9];
    const float* fc_b  = (const float*)d_in[10];
    float* out = (float*)d_out;

    // smem sized for layer-1 layout: sW + sV + sP + sB + sC
    const int SMB = (64 * (HH + HH + 4) + (HH + HH) * 16 + 8 * 64 * 18 + 64 + 256) * 4; // 203,008

    cudaFuncSetAttribute(rnn_fused, cudaFuncAttributeMaxDynamicSharedMemorySize, SMB);

    rnn_fused<<<128, NT, SMB>>>(x, W_ih0, W_hh0, b_ih0, b_hh0,
                                W_ih1, W_hh1, b_ih1, b_hh1);
    fc_kernel<<<BB, 128>>>(fc_w, fc_b, out);
}